// round 8
// baseline (speedup 1.0000x reference)
#include <cuda_runtime.h>
#include <cstdint>

// ---- static problem config ----
#define HMAP      524288u          // 2^19 entries per level
#define HMASK     (HMAP - 1u)
#define NLEVEL    3
#define NPTS      2097152u         // B
#define TBL_ELEMS (NLEVEL * HMAP)  // 1,572,864
#define NPAIRS    (TBL_ELEMS / 2u) // 786,432
#define PRIME1    2654435761u
#define PRIME2    805459861u

// Pair-packed tables. Tk packs entry pairs {m, m^k} into one aligned float4:
//   Tk[((m & ~k)>>1) + t],  t = min(low, k-low), low = m & k
//   slot lo = member with (m & k) <= k/2; float4 = (lo.c0, lo.c1, hi.c0, hi.c1)
// T1 doubles as the flat float2 table for the scalar fallback.
__device__ __align__(16) float4 g_t1 [NPAIRS];
__device__ __align__(16) float4 g_t3 [NPAIRS];
__device__ __align__(16) float4 g_t7 [NPAIRS];
__device__ __align__(16) float4 g_t15[NPAIRS];

// entry m of the flat multi-level table, read from raw triplane layout
__device__ __forceinline__ float2 ent(const float* __restrict__ tri, unsigned m) {
    unsigned p  = m >> 19;
    unsigned mm = m & HMASK;
    const float* base = tri + (size_t)p * (2u * HMAP);
    return make_float2(base[mm], base[mm + HMAP]);
}

__device__ __forceinline__ float4 pack2(float2 lo, float2 hi) {
    return make_float4(lo.x, lo.y, hi.x, hi.y);
}

// ---------------------------------------------------------------------------
// Pass 1: build the four pair-packed tables from the raw triplane.
// ---------------------------------------------------------------------------
__global__ __launch_bounds__(256) void pack_kernel(const float* __restrict__ tri) {
    unsigned j = blockIdx.x * 256u + threadIdx.x;
    if (j >= NPAIRS) return;

    g_t1[j] = pack2(ent(tri, 2u * j), ent(tri, 2u * j + 1u));
    {   // K=3, group 4
        unsigned b = (j >> 1) << 2, t = j & 1u;
        g_t3[j] = pack2(ent(tri, b + t), ent(tri, b + 3u - t));
    }
    {   // K=7, group 8
        unsigned b = (j >> 2) << 3, t = j & 3u;
        g_t7[j] = pack2(ent(tri, b + t), ent(tri, b + 7u - t));
    }
    {   // K=15, group 16
        unsigned b = (j >> 3) << 4, t = j & 7u;
        g_t15[j] = pack2(ent(tri, b + t), ent(tri, b + 15u - t));
    }
}

// ---------------------------------------------------------------------------
// Pass 2: encode. TWO points per thread; coalesced LDG.64 inputs, one float4
// store. Early x-lerp per corner keeps register pressure low:
//   corner value = wa*(lo - hi) + hi,  wa = hib ? rx : 1-rx.
// ---------------------------------------------------------------------------
__global__ __launch_bounds__(256, 5) void enc_kernel(const float* __restrict__ xin,
                                                     float4* __restrict__ out) {
    const unsigned t = blockIdx.x * 256u + threadIdx.x;   // pair index < NPTS/2

    const float2* __restrict__ x2 = reinterpret_cast<const float2*>(xin);
    const float2 A  = __ldg(&x2[3u * t + 0u]);   // p0.x p0.y
    const float2 Bv = __ldg(&x2[3u * t + 1u]);   // p0.z p1.x
    const float2 Cv = __ldg(&x2[3u * t + 2u]);   // p1.y p1.z

    float cx[2], cy[2], cz[2];
    cx[0] = (A.x  + 1.0f) * 0.5f;  cy[0] = (A.y  + 1.0f) * 0.5f;  cz[0] = (Bv.x + 1.0f) * 0.5f;
    cx[1] = (Bv.y + 1.0f) * 0.5f;  cy[1] = (Cv.x + 1.0f) * 0.5f;  cz[1] = (Cv.y + 1.0f) * 0.5f;

    float accx[2] = {0.0f, 0.0f}, accy[2] = {0.0f, 0.0f};

#pragma unroll
    for (int lv = 0; lv < NLEVEL; lv++) {
        const float scale = (float)((128 << lv) - 1);   // 127, 255, 511

#pragma unroll
        for (int u = 0; u < 2; u++) {
            const float px = cx[u] * scale + 0.5f;
            const float py = cy[u] * scale + 0.5f;
            const float pz = cz[u] * scale + 0.5f;
            const float gx = floorf(px), gy = floorf(py), gz = floorf(pz);
            const float rx = px - gx, ry = py - gy, rz = pz - gz;
            const float wx0 = 1.0f - rx, wx1 = rx;

            const unsigned ix = (unsigned)gx;
            const unsigned iy = (unsigned)gy;
            const unsigned iz = (unsigned)gz;

            const unsigned hy0 = iy * PRIME1;
            const unsigned hy1 = hy0 + PRIME1;
            const unsigned hz0 = iz * PRIME2;
            const unsigned hz1 = hz0 + PRIME2;

            unsigned rr[4];
            rr[0] = hy0 ^ hz0;
            rr[1] = hy1 ^ hz0;
            rr[2] = hy0 ^ hz1;
            rr[3] = hy1 ^ hz1;

            const unsigned lvoff = (unsigned)lv * (HMAP / 2u);
            const unsigned tz = ix ^ (ix + 1u);

            float4 q[4];
            float  wa[4];

            if (tz <= 15u) {
                const float4* __restrict__ tp =
                    (tz == 1u) ? g_t1 : (tz == 3u) ? g_t3 : (tz == 7u) ? g_t7 : g_t15;
                const unsigned half = tz >> 1;
#pragma unroll
                for (int c = 0; c < 4; c++) {
                    const unsigned m   = (ix ^ rr[c]) & HMASK;
                    const unsigned low = m & tz;
                    const bool     hb  = low > half;
                    const unsigned s   = hb ? (tz - low) : low;
                    q[c]  = __ldg(&tp[((m & ~tz) >> 1) + s + lvoff]);
                    wa[c] = hb ? wx1 : wx0;
                }
            } else {
                // rare (6.25%): ix with >=4 trailing ones -> 8 scalar gathers
                const float2* __restrict__ t2 =
                    reinterpret_cast<const float2*>(g_t1) + (unsigned)lv * HMAP;
                const unsigned ix1 = ix + 1u;
#pragma unroll
                for (int c = 0; c < 4; c++) {
                    const float2 fa = __ldg(&t2[(ix  ^ rr[c]) & HMASK]);
                    const float2 fb = __ldg(&t2[(ix1 ^ rr[c]) & HMASK]);
                    q[c]  = make_float4(fa.x, fa.y, fb.x, fb.y);
                    wa[c] = wx0;
                }
            }

            // early x-lerp: collapse each pair into one float2 corner value
            float fx[4], fy[4];
#pragma unroll
            for (int c = 0; c < 4; c++) {
                fx[c] = fmaf(wa[c], q[c].x - q[c].z, q[c].z);
                fy[c] = fmaf(wa[c], q[c].y - q[c].w, q[c].w);
            }

            const float wy0 = 1.0f - ry, wy1 = ry;
            const float wz0 = 1.0f - rz, wz1 = rz;
            float wyz[4];
            wyz[0] = wy0 * wz0;
            wyz[1] = wy1 * wz0;
            wyz[2] = wy0 * wz1;
            wyz[3] = wy1 * wz1;

#pragma unroll
            for (int c = 0; c < 4; c++) {
                accx[u] += wyz[c] * fx[c];
                accy[u] += wyz[c] * fy[c];
            }
        }
    }

    out[t] = make_float4(accx[0], accy[0], accx[1], accy[1]);
}

extern "C" void kernel_launch(void* const* d_in, const int* in_sizes, int n_in,
                              void* d_out, int out_size) {
    const float* tri = (const float*)d_in[0];
    const float* xin = (const float*)d_in[1];
    if (in_sizes[0] != 3145728) {
        tri = (const float*)d_in[1];
        xin = (const float*)d_in[0];
    }
    float4* out = (float4*)d_out;

    pack_kernel<<<(NPAIRS + 255u) / 256u, 256>>>(tri);
    enc_kernel<<<NPTS / 2u / 256u, 256>>>(xin, out);
}